// round 14
// baseline (speedup 1.0000x reference)
#include <cuda_runtime.h>
#include <cuda_fp16.h>
#include <cstddef>

#define N_USERS 200000
#define N_ITEMS 100000
#define N_NODES 300000
#define DIM     64
#define N_EDGES 1200000

#define SCALE     256.0f
#define INV_SCALE (1.0f / 256.0f)

#define SCAN_BLK 1024
#define NB_SCAN  ((N_NODES + SCAN_BLK - 1) / SCAN_BLK)   // 293
static_assert(NB_SCAN <= SCAN_BLK, "scan3 single-load prefix assumption");

#define EDGE_T (N_EDGES / 4)   // 300000 threads, 4 edges each
static_assert(N_EDGES % 4 == 0, "edge batching divisibility");

// fp8(e4m3) copy of emb*256: 64 B/node (uint2 per 8 dims), 19.2 MB.
__device__ uint2 g_embf8[(size_t)N_NODES * 8];
// CSR: degree (zero-invariant across launches), offsets, block sums, buckets.
__device__ int   g_deg[N_NODES];
__device__ int   g_off[N_NODES + 1];
__device__ int   g_bsum[NB_SCAN];
__device__ uint2 g_edge[N_EDGES];     // {col, float bits of val}
__device__ int   g_identity;

__device__ __forceinline__ float sigf_exact(float x) {
    return 1.0f / (1.0f + __expf(-x));
}
// Odd-polynomial sigmoid: rel err < 3e-4 for |t| <= 1; exact fallback beyond.
__device__ __forceinline__ float sigf(float t) {
    if (__builtin_expect(fabsf(t) < 1.0f, 1)) {
        float t2 = t * t;
        float p  = fmaf(t2, 1.0f / 480.0f, -1.0f / 48.0f);
        p        = fmaf(t2, p, 0.25f);
        return fmaf(t, p, 0.5f);
    }
    return sigf_exact(t);
}
__device__ __forceinline__ unsigned short f32x2_to_e4m3x2(float lo, float hi) {
    unsigned short r;
    asm("cvt.rn.satfinite.e4m3x2.f32 %0, %1, %2;" : "=h"(r) : "f"(hi), "f"(lo));
    return r;
}
__device__ __forceinline__ __half2 e4m3x2_to_h2(unsigned v) {
    unsigned r;
    asm("{ .reg .b16 t; cvt.u16.u32 t, %1; cvt.rn.f16x2.e4m3x2 %0, t; }"
        : "=r"(r) : "r"(v));
    return *reinterpret_cast<__half2*>(&r);
}

// ---------------------------------------------------------------------------
// Seed (main stream): out[n,0:64] = emb (f32); g_embf8[n] = fp8(emb*256).
// 8 threads/node. Last block checks filt == I.
// ---------------------------------------------------------------------------
__global__ void seed_kernel(const float4* __restrict__ ue4,
                            const float4* __restrict__ ie4,
                            const float*  __restrict__ filt,
                            float4*       __restrict__ out4) {
    if (blockIdx.x == gridDim.x - 1) {
        __shared__ int ok;
        if (threadIdx.x == 0) ok = 1;
        __syncthreads();
        for (int i = threadIdx.x; i < DIM * DIM; i += blockDim.x) {
            int r = i >> 6, c = i & 63;
            float expect = (r == c) ? 1.0f : 0.0f;
            if (filt[i] != expect) atomicAnd(&ok, 0);
        }
        __syncthreads();
        if (threadIdx.x == 0) g_identity = ok;
        return;
    }
    unsigned idx = blockIdx.x * blockDim.x + threadIdx.x;
    unsigned n = idx >> 3;
    unsigned c = idx & 7u;
    if (n >= (unsigned)N_NODES) return;

    const float4* src = (n < N_USERS) ? (ue4 + (size_t)n * 16)
                                      : (ie4 + (size_t)(n - N_USERS) * 16);
    float4 e0 = __ldg(src + 2 * c);
    float4 e1 = __ldg(src + 2 * c + 1);

    out4[(size_t)n * 32 + 2 * c]     = e0;
    out4[(size_t)n * 32 + 2 * c + 1] = e1;

    unsigned short s0 = f32x2_to_e4m3x2(e0.x * SCALE, e0.y * SCALE);
    unsigned short s1 = f32x2_to_e4m3x2(e0.z * SCALE, e0.w * SCALE);
    unsigned short s2 = f32x2_to_e4m3x2(e1.x * SCALE, e1.y * SCALE);
    unsigned short s3 = f32x2_to_e4m3x2(e1.z * SCALE, e1.w * SCALE);
    uint2 f8;
    f8.x = (unsigned)s0 | ((unsigned)s1 << 16);
    f8.y = (unsigned)s2 | ((unsigned)s3 << 16);
    g_embf8[(size_t)n * 8 + c] = f8;
}

// ---------------------------------------------------------------------------
// Build chain (side stream): hist -> scan1 -> scan3 -> scatter.
// g_deg is all-zero at entry (k_scatter's atomicSub drains it every launch).
// hist/scatter: 4 edges per thread, strided by EDGE_T, loads front-batched
// so 4 independent L2 chains are in flight (MLP=4).
// ---------------------------------------------------------------------------
__global__ void k_hist(const int* __restrict__ rows) {
    unsigned t = blockIdx.x * blockDim.x + threadIdx.x;
    if (t >= (unsigned)EDGE_T) return;
    int r0 = __ldg(rows + t);
    int r1 = __ldg(rows + t + EDGE_T);
    int r2 = __ldg(rows + t + 2 * EDGE_T);
    int r3 = __ldg(rows + t + 3 * EDGE_T);
    atomicAdd(&g_deg[r0], 1);
    atomicAdd(&g_deg[r1], 1);
    atomicAdd(&g_deg[r2], 1);
    atomicAdd(&g_deg[r3], 1);
}

__global__ void k_scan1() {
    __shared__ int wsum[32];
    int i = blockIdx.x * SCAN_BLK + threadIdx.x;
    int v = (i < N_NODES) ? g_deg[i] : 0;
    int lane = threadIdx.x & 31, wid = threadIdx.x >> 5;

    int x = v;
    #pragma unroll
    for (int d = 1; d < 32; d <<= 1) {
        int y = __shfl_up_sync(0xffffffffu, x, d);
        if (lane >= d) x += y;
    }
    if (lane == 31) wsum[wid] = x;
    __syncthreads();
    if (wid == 0) {
        int s = wsum[lane];
        #pragma unroll
        for (int d = 1; d < 32; d <<= 1) {
            int y = __shfl_up_sync(0xffffffffu, s, d);
            if (lane >= d) s += y;
        }
        wsum[lane] = s;
    }
    __syncthreads();
    int warpoff = (wid == 0) ? 0 : wsum[wid - 1];
    if (i < N_NODES) g_off[i] = warpoff + x - v;
    if (threadIdx.x == SCAN_BLK - 1) g_bsum[blockIdx.x] = warpoff + x;
}

__global__ void k_scan3() {
    __shared__ int wsum[32];
    int tid = threadIdx.x;
    int b = blockIdx.x;
    int s = (tid < b) ? g_bsum[tid] : 0;      // b < 1024, one load covers all
    #pragma unroll
    for (int d = 16; d; d >>= 1) s += __shfl_down_sync(0xffffffffu, s, d);
    if ((tid & 31) == 0) wsum[tid >> 5] = s;
    __syncthreads();
    if (tid < 32) {
        int v = wsum[tid];
        #pragma unroll
        for (int d = 16; d; d >>= 1) v += __shfl_down_sync(0xffffffffu, v, d);
        if (tid == 0) wsum[0] = v;
    }
    __syncthreads();
    int pre = wsum[0];
    int i = b * SCAN_BLK + tid;
    if (i < N_NODES) g_off[i] += pre;
    if (i == N_NODES) g_off[N_NODES] = N_EDGES;
}

__global__ void k_scatter(const int*   __restrict__ rows,
                          const int*   __restrict__ cols,
                          const float* __restrict__ vals) {
    unsigned t = blockIdx.x * blockDim.x + threadIdx.x;
    if (t >= (unsigned)EDGE_T) return;
    unsigned e0 = t, e1 = t + EDGE_T, e2 = t + 2 * EDGE_T, e3 = t + 3 * EDGE_T;

    int r0 = __ldg(rows + e0);
    int r1 = __ldg(rows + e1);
    int r2 = __ldg(rows + e2);
    int r3 = __ldg(rows + e3);

    int o0 = __ldg(&g_off[r0]);
    int o1 = __ldg(&g_off[r1]);
    int o2 = __ldg(&g_off[r2]);
    int o3 = __ldg(&g_off[r3]);

    int c0 = __ldg(cols + e0);
    int c1 = __ldg(cols + e1);
    int c2 = __ldg(cols + e2);
    int c3 = __ldg(cols + e3);
    float v0 = __ldg(vals + e0);
    float v1 = __ldg(vals + e1);
    float v2 = __ldg(vals + e2);
    float v3 = __ldg(vals + e3);

    int p0 = o0 + atomicSub(&g_deg[r0], 1) - 1;
    int p1 = o1 + atomicSub(&g_deg[r1], 1) - 1;
    int p2 = o2 + atomicSub(&g_deg[r2], 1) - 1;
    int p3 = o3 + atomicSub(&g_deg[r3], 1) - 1;

    uint2 pk;
    pk.x = (unsigned)c0; pk.y = __float_as_uint(v0); g_edge[p0] = pk;
    pk.x = (unsigned)c1; pk.y = __float_as_uint(v1); g_edge[p1] = pk;
    pk.x = (unsigned)c2; pk.y = __float_as_uint(v2); g_edge[p2] = pk;
    pk.x = (unsigned)c3; pk.y = __float_as_uint(v3); g_edge[p3] = pk;
}

// ---------------------------------------------------------------------------
// Consume + epilogue fused: 8 threads/node, half2 HFMA2 accumulation in the
// scaled domain. blockDim 256 (32 nodes/block).
// ---------------------------------------------------------------------------
__global__ void k_consume(const float* __restrict__ filt,
                          float4*      __restrict__ out4) {
    unsigned idx = blockIdx.x * blockDim.x + threadIdx.x;
    unsigned n = idx >> 3;
    unsigned c = idx & 7u;
    bool active = (n < (unsigned)N_NODES);

    __half2 acc0, acc1, acc2, acc3;
    acc0 = acc1 = acc2 = acc3 = __half2half2(__ushort_as_half(0));
    if (active) {
        uint2 eb = g_embf8[(size_t)n * 8 + c];
        const __half2 two = __half2half2(__float2half(2.0f));
        acc0 = __hmul2(e4m3x2_to_h2(eb.x),       two);
        acc1 = __hmul2(e4m3x2_to_h2(eb.x >> 16), two);
        acc2 = __hmul2(e4m3x2_to_h2(eb.y),       two);
        acc3 = __hmul2(e4m3x2_to_h2(eb.y >> 16), two);

        int p   = __ldg(&g_off[n]);
        int end = __ldg(&g_off[n + 1]);
        for (; p < end; ++p) {
            uint2 pk = __ldg(&g_edge[p]);
            uint2 xb = __ldg(&g_embf8[(size_t)pk.x * 8 + c]);
            __half2 vv = __float2half2_rn(-__uint_as_float(pk.y));
            acc0 = __hfma2(e4m3x2_to_h2(xb.x),       vv, acc0);
            acc1 = __hfma2(e4m3x2_to_h2(xb.x >> 16), vv, acc1);
            acc2 = __hfma2(e4m3x2_to_h2(xb.y),       vv, acc2);
            acc3 = __hfma2(e4m3x2_to_h2(xb.y >> 16), vv, acc3);
        }
    }

    float2 f0 = __half22float2(acc0);
    float2 f1 = __half22float2(acc1);
    float2 f2 = __half22float2(acc2);
    float2 f3 = __half22float2(acc3);
    float t[8] = { f0.x * INV_SCALE, f0.y * INV_SCALE,
                   f1.x * INV_SCALE, f1.y * INV_SCALE,
                   f2.x * INV_SCALE, f2.y * INV_SCALE,
                   f3.x * INV_SCALE, f3.y * INV_SCALE };

    if (g_identity) {
        if (active) {
            float4 h0 = make_float4(sigf(t[0]), sigf(t[1]), sigf(t[2]), sigf(t[3]));
            float4 h1 = make_float4(sigf(t[4]), sigf(t[5]), sigf(t[6]), sigf(t[7]));
            out4[(size_t)n * 32 + 16 + 2 * c]     = h0;
            out4[(size_t)n * 32 + 16 + 2 * c + 1] = h1;
        }
    } else {
        __shared__ float ts[32][DIM];
        unsigned ln = threadIdx.x >> 3;
        float* tr = ts[ln] + c * 8;
        #pragma unroll
        for (int j = 0; j < 8; j++) tr[j] = t[j];
        __syncthreads();
        if (active) {
            const float* trow = ts[ln];
            float s[8] = {0.f};
            #pragma unroll 8
            for (int k = 0; k < DIM; k++) {
                float tk = trow[k];
                const float* frow = filt + (size_t)k * DIM + c * 8;
                #pragma unroll
                for (int j = 0; j < 8; j++) s[j] += tk * frow[j];
            }
            float4 h0 = make_float4(sigf_exact(s[0]), sigf_exact(s[1]),
                                    sigf_exact(s[2]), sigf_exact(s[3]));
            float4 h1 = make_float4(sigf_exact(s[4]), sigf_exact(s[5]),
                                    sigf_exact(s[6]), sigf_exact(s[7]));
            out4[(size_t)n * 32 + 16 + 2 * c]     = h0;
            out4[(size_t)n * 32 + 16 + 2 * c + 1] = h1;
        }
    }
}

// ---------------------------------------------------------------------------
// Launch: CSR build on a side stream overlapping the DRAM-bound seed;
// consume joins both. (Fork/join validated capturable in Rounds 5/12.)
// ---------------------------------------------------------------------------
extern "C" void kernel_launch(void* const* d_in, const int* in_sizes, int n_in,
                              void* d_out, int out_size) {
    const int*   rows = (const int*)  d_in[0];
    const int*   cols = (const int*)  d_in[1];
    const float* vals = (const float*)d_in[2];
    const float* ue   = (const float*)d_in[3];
    const float* ie   = (const float*)d_in[4];
    const float* filt = (const float*)d_in[5];
    float4*      out4 = (float4*)d_out;

    static cudaStream_t s_side = nullptr;
    static cudaEvent_t  ev_fork = nullptr, ev_join = nullptr;
    if (s_side == nullptr) {
        cudaStreamCreateWithFlags(&s_side, cudaStreamNonBlocking);
        cudaEventCreateWithFlags(&ev_fork, cudaEventDisableTiming);
        cudaEventCreateWithFlags(&ev_join, cudaEventDisableTiming);
    }

    cudaEventRecord(ev_fork, 0);
    cudaStreamWaitEvent(s_side, ev_fork, 0);

    // Side stream: CSR build (4 edges/thread in hist & scatter).
    const unsigned ebt_blocks = (EDGE_T + 255) / 256;            // 1172
    k_hist<<<ebt_blocks, 256, 0, s_side>>>(rows);
    k_scan1<<<NB_SCAN, SCAN_BLK, 0, s_side>>>();
    k_scan3<<<NB_SCAN, SCAN_BLK, 0, s_side>>>();
    k_scatter<<<ebt_blocks, 256, 0, s_side>>>(rows, cols, vals);
    cudaEventRecord(ev_join, s_side);

    // Main stream: seed.
    const unsigned seed_threads = (unsigned)N_NODES * 8u;        // 2.4M
    const unsigned seed_blocks  = (seed_threads + 255) / 256;
    seed_kernel<<<seed_blocks + 1, 256>>>(
        (const float4*)ue, (const float4*)ie, filt, out4);

    // Join, then consume.
    cudaStreamWaitEvent(0, ev_join, 0);
    const unsigned cons_threads = (unsigned)N_NODES * 8u;        // 2.4M
    k_consume<<<(cons_threads + 255) / 256, 256>>>(filt, out4);
}

// round 15
// speedup vs baseline: 1.2707x; 1.2707x over previous
#include <cuda_runtime.h>
#include <cuda_fp16.h>
#include <cstddef>

#define N_USERS 200000
#define N_ITEMS 100000
#define N_NODES 300000
#define DIM     64
#define N_EDGES 1200000

#define SCALE     256.0f
#define INV_SCALE (1.0f / 256.0f)

#define SCAN_BLK 1024
#define NB_SCAN  ((N_NODES + SCAN_BLK - 1) / SCAN_BLK)   // 293
static_assert(NB_SCAN <= SCAN_BLK, "scan3 single-load prefix assumption");

// fp8(e4m3) copy of emb*256: 64 B/node (uint2 per 8 dims), 19.2 MB.
__device__ uint2 g_embf8[(size_t)N_NODES * 8];
// CSR: degree (zero-invariant across launches), offsets, block sums, buckets.
__device__ int   g_deg[N_NODES];
__device__ int   g_off[N_NODES + 1];
__device__ int   g_bsum[NB_SCAN];
__device__ uint2 g_edge[N_EDGES];     // {col, float bits of val}
__device__ int   g_identity;

__device__ __forceinline__ float sigf_exact(float x) {
    return 1.0f / (1.0f + __expf(-x));
}
// Odd-polynomial sigmoid: rel err < 3e-4 for |t| <= 1; exact fallback beyond.
__device__ __forceinline__ float sigf(float t) {
    if (__builtin_expect(fabsf(t) < 1.0f, 1)) {
        float t2 = t * t;
        float p  = fmaf(t2, 1.0f / 480.0f, -1.0f / 48.0f);
        p        = fmaf(t2, p, 0.25f);
        return fmaf(t, p, 0.5f);
    }
    return sigf_exact(t);
}
__device__ __forceinline__ unsigned short f32x2_to_e4m3x2(float lo, float hi) {
    unsigned short r;
    asm("cvt.rn.satfinite.e4m3x2.f32 %0, %1, %2;" : "=h"(r) : "f"(hi), "f"(lo));
    return r;
}
__device__ __forceinline__ __half2 e4m3x2_to_h2(unsigned v) {
    unsigned r;
    asm("{ .reg .b16 t; cvt.u16.u32 t, %1; cvt.rn.f16x2.e4m3x2 %0, t; }"
        : "=r"(r) : "r"(v));
    return *reinterpret_cast<__half2*>(&r);
}

// ---------------------------------------------------------------------------
// Seed (main stream): out[n,0:64] = emb (f32); g_embf8[n] = fp8(emb*256).
// 8 threads/node. Last block checks filt == I.
// ---------------------------------------------------------------------------
__global__ void seed_kernel(const float4* __restrict__ ue4,
                            const float4* __restrict__ ie4,
                            const float*  __restrict__ filt,
                            float4*       __restrict__ out4) {
    if (blockIdx.x == gridDim.x - 1) {
        __shared__ int ok;
        if (threadIdx.x == 0) ok = 1;
        __syncthreads();
        for (int i = threadIdx.x; i < DIM * DIM; i += blockDim.x) {
            int r = i >> 6, c = i & 63;
            float expect = (r == c) ? 1.0f : 0.0f;
            if (filt[i] != expect) atomicAnd(&ok, 0);
        }
        __syncthreads();
        if (threadIdx.x == 0) g_identity = ok;
        return;
    }
    unsigned idx = blockIdx.x * blockDim.x + threadIdx.x;
    unsigned n = idx >> 3;
    unsigned c = idx & 7u;
    if (n >= (unsigned)N_NODES) return;

    const float4* src = (n < N_USERS) ? (ue4 + (size_t)n * 16)
                                      : (ie4 + (size_t)(n - N_USERS) * 16);
    float4 e0 = __ldg(src + 2 * c);
    float4 e1 = __ldg(src + 2 * c + 1);

    out4[(size_t)n * 32 + 2 * c]     = e0;
    out4[(size_t)n * 32 + 2 * c + 1] = e1;

    unsigned short s0 = f32x2_to_e4m3x2(e0.x * SCALE, e0.y * SCALE);
    unsigned short s1 = f32x2_to_e4m3x2(e0.z * SCALE, e0.w * SCALE);
    unsigned short s2 = f32x2_to_e4m3x2(e1.x * SCALE, e1.y * SCALE);
    unsigned short s3 = f32x2_to_e4m3x2(e1.z * SCALE, e1.w * SCALE);
    uint2 f8;
    f8.x = (unsigned)s0 | ((unsigned)s1 << 16);
    f8.y = (unsigned)s2 | ((unsigned)s3 << 16);
    g_embf8[(size_t)n * 8 + c] = f8;
}

// ---------------------------------------------------------------------------
// Build chain (side stream): hist -> scan1 -> scan3 -> scatter.
// One edge per thread (R12 proven shape — max warp-level parallelism).
// g_deg is all-zero at entry (k_scatter's atomicSub drains it every launch).
// ---------------------------------------------------------------------------
__global__ void k_hist(const int* __restrict__ rows) {
    unsigned e = blockIdx.x * blockDim.x + threadIdx.x;
    if (e < (unsigned)N_EDGES) atomicAdd(&g_deg[__ldg(rows + e)], 1);
}

__global__ void k_scan1() {
    __shared__ int wsum[32];
    int i = blockIdx.x * SCAN_BLK + threadIdx.x;
    int v = (i < N_NODES) ? g_deg[i] : 0;
    int lane = threadIdx.x & 31, wid = threadIdx.x >> 5;

    int x = v;
    #pragma unroll
    for (int d = 1; d < 32; d <<= 1) {
        int y = __shfl_up_sync(0xffffffffu, x, d);
        if (lane >= d) x += y;
    }
    if (lane == 31) wsum[wid] = x;
    __syncthreads();
    if (wid == 0) {
        int s = wsum[lane];
        #pragma unroll
        for (int d = 1; d < 32; d <<= 1) {
            int y = __shfl_up_sync(0xffffffffu, s, d);
            if (lane >= d) s += y;
        }
        wsum[lane] = s;
    }
    __syncthreads();
    int warpoff = (wid == 0) ? 0 : wsum[wid - 1];
    if (i < N_NODES) g_off[i] = warpoff + x - v;
    if (threadIdx.x == SCAN_BLK - 1) g_bsum[blockIdx.x] = warpoff + x;
}

__global__ void k_scan3() {
    __shared__ int wsum[32];
    int tid = threadIdx.x;
    int b = blockIdx.x;
    int s = (tid < b) ? g_bsum[tid] : 0;      // b < 1024, one load covers all
    #pragma unroll
    for (int d = 16; d; d >>= 1) s += __shfl_down_sync(0xffffffffu, s, d);
    if ((tid & 31) == 0) wsum[tid >> 5] = s;
    __syncthreads();
    if (tid < 32) {
        int v = wsum[tid];
        #pragma unroll
        for (int d = 16; d; d >>= 1) v += __shfl_down_sync(0xffffffffu, v, d);
        if (tid == 0) wsum[0] = v;
    }
    __syncthreads();
    int pre = wsum[0];
    int i = b * SCAN_BLK + tid;
    if (i < N_NODES) g_off[i] += pre;
    if (i == N_NODES) g_off[N_NODES] = N_EDGES;
}

__global__ void k_scatter(const int*   __restrict__ rows,
                          const int*   __restrict__ cols,
                          const float* __restrict__ vals) {
    unsigned e = blockIdx.x * blockDim.x + threadIdx.x;
    if (e >= (unsigned)N_EDGES) return;
    int r = __ldg(rows + e);
    int pos = __ldg(&g_off[r]) + atomicSub(&g_deg[r], 1) - 1;
    uint2 pk;
    pk.x = (unsigned)__ldg(cols + e);
    pk.y = __float_as_uint(__ldg(vals + e));
    g_edge[pos] = pk;
}

// ---------------------------------------------------------------------------
// Consume + epilogue fused: 8 threads/node, half2 HFMA2 accumulation in the
// scaled domain. Edge-record loads software-pipelined one iteration ahead so
// the record load for edge p+1 overlaps the gather for edge p (breaks the
// 2-deep dependent L2 chain). blockDim 256 (32 nodes/block).
// ---------------------------------------------------------------------------
__global__ void k_consume(const float* __restrict__ filt,
                          float4*      __restrict__ out4) {
    unsigned idx = blockIdx.x * blockDim.x + threadIdx.x;
    unsigned n = idx >> 3;
    unsigned c = idx & 7u;
    bool active = (n < (unsigned)N_NODES);

    __half2 acc0, acc1, acc2, acc3;
    acc0 = acc1 = acc2 = acc3 = __half2half2(__ushort_as_half(0));
    if (active) {
        uint2 eb = g_embf8[(size_t)n * 8 + c];
        const __half2 two = __half2half2(__float2half(2.0f));
        acc0 = __hmul2(e4m3x2_to_h2(eb.x),       two);
        acc1 = __hmul2(e4m3x2_to_h2(eb.x >> 16), two);
        acc2 = __hmul2(e4m3x2_to_h2(eb.y),       two);
        acc3 = __hmul2(e4m3x2_to_h2(eb.y >> 16), two);

        int p   = __ldg(&g_off[n]);
        int end = __ldg(&g_off[n + 1]);
        if (p < end) {
            uint2 pk = __ldg(&g_edge[p]);          // prologue: first record
            while (true) {
                // issue gather for current edge immediately (address ready)
                uint2 xb = __ldg(&g_embf8[(size_t)pk.x * 8 + c]);
                float vcur = __uint_as_float(pk.y);
                ++p;
                bool more = (p < end);
                uint2 pk_next;
                if (more) pk_next = __ldg(&g_edge[p]);   // overlaps gather
                __half2 vv = __float2half2_rn(-vcur);
                acc0 = __hfma2(e4m3x2_to_h2(xb.x),       vv, acc0);
                acc1 = __hfma2(e4m3x2_to_h2(xb.x >> 16), vv, acc1);
                acc2 = __hfma2(e4m3x2_to_h2(xb.y),       vv, acc2);
                acc3 = __hfma2(e4m3x2_to_h2(xb.y >> 16), vv, acc3);
                if (!more) break;
                pk = pk_next;
            }
        }
    }

    float2 f0 = __half22float2(acc0);
    float2 f1 = __half22float2(acc1);
    float2 f2 = __half22float2(acc2);
    float2 f3 = __half22float2(acc3);
    float t[8] = { f0.x * INV_SCALE, f0.y * INV_SCALE,
                   f1.x * INV_SCALE, f1.y * INV_SCALE,
                   f2.x * INV_SCALE, f2.y * INV_SCALE,
                   f3.x * INV_SCALE, f3.y * INV_SCALE };

    if (g_identity) {
        if (active) {
            float4 h0 = make_float4(sigf(t[0]), sigf(t[1]), sigf(t[2]), sigf(t[3]));
            float4 h1 = make_float4(sigf(t[4]), sigf(t[5]), sigf(t[6]), sigf(t[7]));
            out4[(size_t)n * 32 + 16 + 2 * c]     = h0;
            out4[(size_t)n * 32 + 16 + 2 * c + 1] = h1;
        }
    } else {
        __shared__ float ts[32][DIM];
        unsigned ln = threadIdx.x >> 3;
        float* tr = ts[ln] + c * 8;
        #pragma unroll
        for (int j = 0; j < 8; j++) tr[j] = t[j];
        __syncthreads();
        if (active) {
            const float* trow = ts[ln];
            float s[8] = {0.f};
            #pragma unroll 8
            for (int k = 0; k < DIM; k++) {
                float tk = trow[k];
                const float* frow = filt + (size_t)k * DIM + c * 8;
                #pragma unroll
                for (int j = 0; j < 8; j++) s[j] += tk * frow[j];
            }
            float4 h0 = make_float4(sigf_exact(s[0]), sigf_exact(s[1]),
                                    sigf_exact(s[2]), sigf_exact(s[3]));
            float4 h1 = make_float4(sigf_exact(s[4]), sigf_exact(s[5]),
                                    sigf_exact(s[6]), sigf_exact(s[7]));
            out4[(size_t)n * 32 + 16 + 2 * c]     = h0;
            out4[(size_t)n * 32 + 16 + 2 * c + 1] = h1;
        }
    }
}

// ---------------------------------------------------------------------------
// Launch: CSR build on a side stream overlapping the DRAM-bound seed;
// consume joins both. (Fork/join validated capturable in Rounds 5/12.)
// ---------------------------------------------------------------------------
extern "C" void kernel_launch(void* const* d_in, const int* in_sizes, int n_in,
                              void* d_out, int out_size) {
    const int*   rows = (const int*)  d_in[0];
    const int*   cols = (const int*)  d_in[1];
    const float* vals = (const float*)d_in[2];
    const float* ue   = (const float*)d_in[3];
    const float* ie   = (const float*)d_in[4];
    const float* filt = (const float*)d_in[5];
    float4*      out4 = (float4*)d_out;

    static cudaStream_t s_side = nullptr;
    static cudaEvent_t  ev_fork = nullptr, ev_join = nullptr;
    if (s_side == nullptr) {
        cudaStreamCreateWithFlags(&s_side, cudaStreamNonBlocking);
        cudaEventCreateWithFlags(&ev_fork, cudaEventDisableTiming);
        cudaEventCreateWithFlags(&ev_join, cudaEventDisableTiming);
    }

    cudaEventRecord(ev_fork, 0);
    cudaStreamWaitEvent(s_side, ev_fork, 0);

    // Side stream: CSR build (R12 shapes: one edge per thread).
    const unsigned edge_blocks = (N_EDGES + 255) / 256;          // 4688
    k_hist<<<edge_blocks, 256, 0, s_side>>>(rows);
    k_scan1<<<NB_SCAN, SCAN_BLK, 0, s_side>>>();
    k_scan3<<<NB_SCAN, SCAN_BLK, 0, s_side>>>();
    k_scatter<<<edge_blocks, 256, 0, s_side>>>(rows, cols, vals);
    cudaEventRecord(ev_join, s_side);

    // Main stream: seed.
    const unsigned seed_threads = (unsigned)N_NODES * 8u;        // 2.4M
    const unsigned seed_blocks  = (seed_threads + 255) / 256;
    seed_kernel<<<seed_blocks + 1, 256>>>(
        (const float4*)ue, (const float4*)ie, filt, out4);

    // Join, then consume.
    cudaStreamWaitEvent(0, ev_join, 0);
    const unsigned cons_threads = (unsigned)N_NODES * 8u;        // 2.4M
    k_consume<<<(cons_threads + 255) / 256, 256>>>(filt, out4);
}